// round 5
// baseline (speedup 1.0000x reference)
#include <cuda_runtime.h>
#include <math.h>

#define PATCH 7
#define PP 49

#define BM 64
#define BN 64
#define BK 16
#define NSPLIT 4
#define AS_STRIDE (BM + 4)   // 68 floats; 68*4B multiple of 16 -> LDS.128 ok

// Scratch buffers
__device__ float g_buf0[1 << 19];   // activations ping
__device__ float g_buf1[1 << 19];   // activations pong
__device__ float g_part[1 << 20];   // 4 x (1024*256) partial products

// ---------------------------------------------------------------------------
// Partial GEMM: C_part[s] = A[:, s*Ks:(s+1)*Ks] @ W[s*Ks:(s+1)*Ks, :]
// BM=64, BN=64, BK=16, 128 threads, per-thread 8x4 tile.
// A staged k-major (As[k][row]); double-buffered smem, register prefetch.
// ---------------------------------------------------------------------------
__global__ void __launch_bounds__(128)
gemm_partial_kernel(const float* __restrict__ A, const float* __restrict__ W,
                    float* __restrict__ Cpart, int M, int N, int K) {
    __shared__ float As[2][BK][AS_STRIDE];
    __shared__ float Bs[2][BK][BN];

    const int tid = threadIdx.x;
    const int block_m = blockIdx.y * BM;
    const int block_n = blockIdx.x * BN;
    const int s = blockIdx.z;
    const int Ks = K / NSPLIT;                 // 64
    const int k0s = s * Ks;

    // A global-load mapping: row = tid&63, kg = tid>>6 (0/1), 8 consecutive k
    const int a_row = tid & 63;
    const int a_kg  = tid >> 6;
    const bool a_ok = (block_m + a_row) < M;
    const size_t a_base = (size_t)(block_m + a_row) * K + k0s + a_kg * 8;

    // B global-load mapping: r = tid>>3 (0..15), c = (tid&7)*8
    const int b_r = tid >> 3;
    const int b_c = (tid & 7) * 8;
    const size_t w_base = (size_t)(k0s + b_r) * N + block_n + b_c;

    // Compute mapping: ty = row group (8 rows), tx = col group (4 cols)
    const int tx = tid & 15;
    const int ty = tid >> 4;

    float4 aR0, aR1;        // A prefetch: 8 consecutive k for one row
    float4 bR0, bR1;        // B prefetch: 8 consecutive n for one k-row

    // ---- load tile 0 ----
    if (a_ok) {
        aR0 = *reinterpret_cast<const float4*>(&A[a_base]);
        aR1 = *reinterpret_cast<const float4*>(&A[a_base + 4]);
    } else {
        aR0 = aR1 = make_float4(0.f, 0.f, 0.f, 0.f);
    }
    bR0 = *reinterpret_cast<const float4*>(&W[w_base]);
    bR1 = *reinterpret_cast<const float4*>(&W[w_base + 4]);

    {
        const float* av0 = &aR0.x;
        const float* av1 = &aR1.x;
#pragma unroll
        for (int j = 0; j < 4; j++) As[0][a_kg * 8 + j][a_row] = av0[j];
#pragma unroll
        for (int j = 0; j < 4; j++) As[0][a_kg * 8 + 4 + j][a_row] = av1[j];
        *reinterpret_cast<float4*>(&Bs[0][b_r][b_c]) = bR0;
        *reinterpret_cast<float4*>(&Bs[0][b_r][b_c + 4]) = bR1;
    }
    __syncthreads();

    float acc[8][4];
#pragma unroll
    for (int i = 0; i < 8; i++)
#pragma unroll
        for (int j = 0; j < 4; j++) acc[i][j] = 0.f;

    const int nt = Ks / BK;                    // 4
    int cur = 0;

    for (int t = 0; t < nt; t++) {
        if (t + 1 < nt) {
            const size_t koff = (size_t)(t + 1) * BK;
            if (a_ok) {
                aR0 = *reinterpret_cast<const float4*>(&A[a_base + koff]);
                aR1 = *reinterpret_cast<const float4*>(&A[a_base + koff + 4]);
            }
            bR0 = *reinterpret_cast<const float4*>(&W[w_base + koff * N]);
            bR1 = *reinterpret_cast<const float4*>(&W[w_base + koff * N + 4]);
        }

#pragma unroll
        for (int kk = 0; kk < BK; kk++) {
            float4 a0 = *reinterpret_cast<const float4*>(&As[cur][kk][ty * 8]);
            float4 a1 = *reinterpret_cast<const float4*>(&As[cur][kk][ty * 8 + 4]);
            float4 b0 = *reinterpret_cast<const float4*>(&Bs[cur][kk][tx * 4]);
            float a[8] = {a0.x, a0.y, a0.z, a0.w, a1.x, a1.y, a1.z, a1.w};
            float b[4] = {b0.x, b0.y, b0.z, b0.w};
#pragma unroll
            for (int i = 0; i < 8; i++)
#pragma unroll
                for (int j = 0; j < 4; j++)
                    acc[i][j] = fmaf(a[i], b[j], acc[i][j]);
        }

        if (t + 1 < nt) {
            const int nxt = cur ^ 1;
            const float* av0 = &aR0.x;
            const float* av1 = &aR1.x;
#pragma unroll
            for (int j = 0; j < 4; j++) As[nxt][a_kg * 8 + j][a_row] = av0[j];
#pragma unroll
            for (int j = 0; j < 4; j++) As[nxt][a_kg * 8 + 4 + j][a_row] = av1[j];
            *reinterpret_cast<float4*>(&Bs[nxt][b_r][b_c]) = bR0;
            *reinterpret_cast<float4*>(&Bs[nxt][b_r][b_c + 4]) = bR1;
        }
        __syncthreads();
        cur ^= 1;
    }

    // epilogue: store raw partials
    float* out = Cpart + (size_t)s * M * N;
    const int col = block_n + tx * 4;
#pragma unroll
    for (int i = 0; i < 8; i++) {
        const int row = block_m + ty * 8 + i;
        if (row < M) {
            float4 v = make_float4(acc[i][0], acc[i][1], acc[i][2], acc[i][3]);
            *reinterpret_cast<float4*>(&out[(size_t)row * N + col]) = v;
        }
    }
}

// ---------------------------------------------------------------------------
// Combine 4 partials + bias (+ReLU). One float4 per thread.
// ---------------------------------------------------------------------------
template <bool RELU>
__global__ void __launch_bounds__(256)
combine_kernel(const float* __restrict__ Cpart, const float* __restrict__ bias,
               float* __restrict__ C, int M, int N) {
    const int idx4 = blockIdx.x * blockDim.x + threadIdx.x;
    const int total4 = M * N / 4;
    if (idx4 >= total4) return;
    const size_t stride = (size_t)M * N;

    const float4* p0 = reinterpret_cast<const float4*>(Cpart);
    const float4* p1 = reinterpret_cast<const float4*>(Cpart + stride);
    const float4* p2 = reinterpret_cast<const float4*>(Cpart + 2 * stride);
    const float4* p3 = reinterpret_cast<const float4*>(Cpart + 3 * stride);

    float4 v0 = p0[idx4], v1 = p1[idx4], v2 = p2[idx4], v3 = p3[idx4];
    float4 bb = reinterpret_cast<const float4*>(bias)[idx4 & (N / 4 - 1)];

    float4 r;
    r.x = (v0.x + v1.x) + (v2.x + v3.x) + bb.x;
    r.y = (v0.y + v1.y) + (v2.y + v3.y) + bb.y;
    r.z = (v0.z + v1.z) + (v2.z + v3.z) + bb.z;
    r.w = (v0.w + v1.w) + (v2.w + v3.w) + bb.w;
    if (RELU) {
        r.x = fmaxf(r.x, 0.f);
        r.y = fmaxf(r.y, 0.f);
        r.z = fmaxf(r.z, 0.f);
        r.w = fmaxf(r.w, 0.f);
    }
    reinterpret_cast<float4*>(C)[idx4] = r;
}

// ---------------------------------------------------------------------------
// Patch gather + dot + indices. One block (256 threads) per query.
// Output layout in d_out (float32):
//   [0, N*49)        logits (n, py, px)
//   [N*49, N*49*5)   indices as float (n, py, px, {b,y,x,q})
// ---------------------------------------------------------------------------
__global__ void __launch_bounds__(256)
patch_kernel(const float* __restrict__ fm, const float* __restrict__ qe,
             const float* __restrict__ qpos, const int* __restrict__ shapes,
             float* __restrict__ out, int N, int Q, int D) {
    __shared__ float sq[256];
    const int n = blockIdx.x;
    if (n >= N) return;

    const int b = n / Q;
    const int q = n - b * Q;
    const int Hb = shapes[2 * b + 0];
    const int Wb = shapes[2 * b + 1];

    const float posx = qpos[2 * n + 0];
    const float posy = qpos[2 * n + 1];
    const int cy = (int)(posy * (float)Hb);
    const int cx = (int)(posx * (float)Wb);

    for (int d = threadIdx.x; d < D; d += blockDim.x)
        sq[d] = qe[(size_t)n * D + d];
    __syncthreads();

    const int warp = threadIdx.x >> 5;
    const int lane = threadIdx.x & 31;
    const float4* sq4 = reinterpret_cast<const float4*>(sq);
    const float4 q0 = sq4[lane];
    const float4 q1 = sq4[lane + 32];

    float* out_logits = out;
    float* out_idx = out + (size_t)N * PP;

    for (int p = warp; p < PP; p += 8) {
        const int dy = p / PATCH - PATCH / 2;
        const int dx = p % PATCH - PATCH / 2;
        int y = cy + dy;
        int x = cx + dx;
        y = min(max(y, 0), Hb - 1);
        x = min(max(x, 0), Wb - 1);

        const size_t row_off = (((size_t)b * Hb + y) * Wb + x) * (size_t)D;
        const float4* row = reinterpret_cast<const float4*>(fm + row_off);

        const float4 f0 = row[lane];
        const float4 f1 = row[lane + 32];

        float s = f0.x * q0.x + f0.y * q0.y + f0.z * q0.z + f0.w * q0.w;
        s = fmaf(f1.x, q1.x, s);
        s = fmaf(f1.y, q1.y, s);
        s = fmaf(f1.z, q1.z, s);
        s = fmaf(f1.w, q1.w, s);

#pragma unroll
        for (int off = 16; off; off >>= 1)
            s += __shfl_xor_sync(0xFFFFFFFFu, s, off);

        if (lane == 0) {
            out_logits[(size_t)n * PP + p] = s;
            float4 iv = make_float4((float)b, (float)y, (float)x, (float)q);
            *reinterpret_cast<float4*>(&out_idx[((size_t)n * PP + p) * 4]) = iv;
        }
    }
}

extern "C" void kernel_launch(void* const* d_in, const int* in_sizes, int n_in,
                              void* d_out, int out_size) {
    const float* fm      = (const float*)d_in[0];
    const float* queries = (const float*)d_in[1];
    const float* qpos    = (const float*)d_in[2];
    const int*   shapes  = (const int*)d_in[4];
    const float* W0 = (const float*)d_in[5];
    const float* b0 = (const float*)d_in[6];
    const float* W1 = (const float*)d_in[7];
    const float* b1 = (const float*)d_in[8];
    const float* W2 = (const float*)d_in[9];
    const float* b2 = (const float*)d_in[10];
    const float* W3 = (const float*)d_in[11];
    const float* b3 = (const float*)d_in[12];

    const int B = in_sizes[3];               // query_batch_offsets length
    const int D = in_sizes[6];               // bias length
    const int N = in_sizes[1] / D;           // total queries
    const int Q = N / B;

    float* buf0;
    float* buf1;
    float* part;
    cudaGetSymbolAddress((void**)&buf0, g_buf0);
    cudaGetSymbolAddress((void**)&buf1, g_buf1);
    cudaGetSymbolAddress((void**)&part, g_part);

    dim3 gblock(128);
    dim3 ggrid(D / BN, (N + BM - 1) / BM, NSPLIT);   // (4, 16, 4) = 256 blocks
    const int total4 = N * D / 4;
    dim3 cgrid((total4 + 255) / 256);

    // layer 0
    gemm_partial_kernel<<<ggrid, gblock>>>(queries, W0, part, N, D, D);
    combine_kernel<true ><<<cgrid, 256>>>(part, b0, buf0, N, D);
    // layer 1
    gemm_partial_kernel<<<ggrid, gblock>>>(buf0, W1, part, N, D, D);
    combine_kernel<true ><<<cgrid, 256>>>(part, b1, buf1, N, D);
    // layer 2
    gemm_partial_kernel<<<ggrid, gblock>>>(buf1, W2, part, N, D, D);
    combine_kernel<true ><<<cgrid, 256>>>(part, b2, buf0, N, D);
    // layer 3 (no relu)
    gemm_partial_kernel<<<ggrid, gblock>>>(buf0, W3, part, N, D, D);
    combine_kernel<false><<<cgrid, 256>>>(part, b3, buf1, N, D);

    patch_kernel<<<N, 256>>>(fm, buf1, qpos, shapes, (float*)d_out, N, Q, D);
}